// round 1
// baseline (speedup 1.0000x reference)
#include <cuda_runtime.h>
#include <cuda_bf16.h>
#include <math.h>

#define S 4096
#define D 256
#define L 4
#define E 4
#define V 32000
#define KGATE 2201   // int(4096 * sigmoid(0.15))

// ---------------- device scratch (no allocations allowed) ----------------
__device__ float g_x[S * D];          // activations, 4 MB
__device__ float g_y[S * E * D];      // all-expert outputs, 16 MB
__device__ float g_scores[S];
__device__ float g_mu[D];
__device__ float g_istd[D];
__device__ float g_absnb[D];
__device__ float g_thr[1];
__device__ float g_mask[S * E];

// ---------------- embedding gather ----------------
__global__ void embed_kernel(const int* __restrict__ tokens,
                             const float* __restrict__ emb) {
    int s = blockIdx.x;
    int d = threadIdx.x;
    int t = tokens[s];
    g_x[s * D + d] = emb[(size_t)t * D + d];
}

// ---------------- AstroNorm column stats (mean/var over S per dim) ----------------
__global__ void stats_kernel(const float* __restrict__ buffers,
                             const float* __restrict__ decays, int l) {
    int d = blockIdx.x;
    int tid = threadIdx.x;
    float s = 0.f, s2 = 0.f;
    for (int i = tid; i < S; i += 256) {
        float v = g_x[i * D + d];
        s += v; s2 += v * v;
    }
    __shared__ float sh[256], sh2[256];
    sh[tid] = s; sh2[tid] = s2;
    __syncthreads();
    for (int off = 128; off > 0; off >>= 1) {
        if (tid < off) { sh[tid] += sh[tid + off]; sh2[tid] += sh2[tid + off]; }
        __syncthreads();
    }
    if (tid == 0) {
        float mu = sh[0] / (float)S;
        float var = (sh2[0] - (float)S * mu * mu) / (float)(S - 1); // ddof=1
        g_mu[d] = mu;
        g_istd[d] = rsqrtf(var + 1e-6f);
        float dec = decays[l];
        float nb = dec * buffers[l * D + d] + (1.f - dec) * mu;
        g_absnb[d] = fabsf(nb);
    }
}

// ---------------- apply AstroNorm + gate scores ----------------
__global__ void norm_score_kernel(const float* __restrict__ gate_w, int l) {
    int s = blockIdx.x;
    int d = threadIdx.x;
    float v = g_x[s * D + d];
    float mu = g_mu[d];
    float v2 = (fabsf(v - mu) > g_absnb[d] ? mu : v) * g_istd[d];
    g_x[s * D + d] = v2;
    // score = dot(x_row, gate_w[l])
    __shared__ float sh[256];
    sh[d] = v2 * gate_w[l * D + d];
    __syncthreads();
    for (int off = 128; off > 0; off >>= 1) {
        if (d < off) sh[d] += sh[d + off];
        __syncthreads();
    }
    if (d == 0) g_scores[s] = sh[0];
}

// ---------------- k-th largest via bitonic sort (single block) ----------------
__global__ void select_kernel() {
    __shared__ float sh[S];
    int tid = threadIdx.x;
    const int NT = 1024;
    for (int i = tid; i < S; i += NT) sh[i] = g_scores[i];
    __syncthreads();
    for (int k = 2; k <= S; k <<= 1) {
        for (int j = k >> 1; j > 0; j >>= 1) {
            for (int i = tid; i < S; i += NT) {
                int ixj = i ^ j;
                if (ixj > i) {
                    float a = sh[i], b = sh[ixj];
                    bool up = ((i & k) == 0);  // ascending subsequence
                    if (up ? (a > b) : (a < b)) { sh[i] = b; sh[ixj] = a; }
                }
            }
            __syncthreads();
        }
    }
    if (tid == 0) g_thr[0] = sh[S - KGATE];  // k-th largest
}

// ---------------- sparsity gate + expert routing mask ----------------
__global__ void gate_mask_kernel(const float* __restrict__ gating_W,
                                 const float* __restrict__ gating_b, int l) {
    int s = blockIdx.x;
    int d = threadIdx.x;
    float thr = g_thr[0];
    bool keep = g_scores[s] > thr;    // strict, matches (scores > thr)
    float v = keep ? g_x[s * D + d] : 0.f;
    g_x[s * D + d] = v;
    // gating scores gs[e] = dot(x, gating_W[l,e]) + gating_b[l,e]
    __shared__ float sh[256];
    __shared__ float gs[E];
    #pragma unroll
    for (int e = 0; e < E; e++) {
        sh[d] = v * gating_W[l * E * D + e * D + d];
        __syncthreads();
        for (int off = 128; off > 0; off >>= 1) {
            if (d < off) sh[d] += sh[d + off];
            __syncthreads();
        }
        if (d == 0) gs[e] = sh[0] + gating_b[l * E + e];
        __syncthreads();
    }
    if (d == 0) {
        // top-3 of 4 == exclude argmin (ties: lax.top_k keeps lower index, so
        // the excluded one is the minimum with the LARGEST index)
        float best = gs[0]; int excl = 0;
        #pragma unroll
        for (int e = 1; e < E; e++) {
            if (gs[e] <= best) { best = gs[e]; excl = e; }
        }
        #pragma unroll
        for (int e = 0; e < E; e++)
            g_mask[s * E + e] = (e == excl) ? 0.f : 1.f;
    }
}

// ---------------- SGEMM: C[M,N] = A[M,K] * B[N,K]^T (+bias) ----------------
// A row-major [M,K], B row-major [N,K]. 128x128 block tile, 8x8 per thread.
#define BM 128
#define BN 128
#define BK 16
#define TM 8
#define TN 8
__global__ __launch_bounds__(256) void sgemm_nt(const float* __restrict__ A,
                                                const float* __restrict__ B,
                                                float* __restrict__ C,
                                                int M, int N, int K,
                                                const float* __restrict__ bias) {
    __shared__ float As[BK][BM];
    __shared__ float Bs[BK][BN];
    int tid = threadIdx.x;
    int tx = tid & 15;       // 0..15 -> N
    int ty = tid >> 4;       // 0..15 -> M
    int row0 = blockIdx.y * BM;
    int col0 = blockIdx.x * BN;
    float acc[TM][TN];
    #pragma unroll
    for (int i = 0; i < TM; i++)
        #pragma unroll
        for (int j = 0; j < TN; j++) acc[i][j] = 0.f;

    for (int k0 = 0; k0 < K; k0 += BK) {
        #pragma unroll
        for (int i = 0; i < 2; i++) {
            int idx = tid + i * 256;          // 0..511
            int r = idx >> 2;                 // 0..127
            int c4 = (idx & 3) << 2;          // 0,4,8,12
            float4 va = *(const float4*)(A + (size_t)(row0 + r) * K + k0 + c4);
            As[c4 + 0][r] = va.x; As[c4 + 1][r] = va.y;
            As[c4 + 2][r] = va.z; As[c4 + 3][r] = va.w;
            float4 vb = *(const float4*)(B + (size_t)(col0 + r) * K + k0 + c4);
            Bs[c4 + 0][r] = vb.x; Bs[c4 + 1][r] = vb.y;
            Bs[c4 + 2][r] = vb.z; Bs[c4 + 3][r] = vb.w;
        }
        __syncthreads();
        #pragma unroll
        for (int kk = 0; kk < BK; kk++) {
            float ra[TM], rb[TN];
            #pragma unroll
            for (int i = 0; i < TM; i++) ra[i] = As[kk][ty * TM + i];
            #pragma unroll
            for (int j = 0; j < TN; j++) rb[j] = Bs[kk][tx * TN + j];
            #pragma unroll
            for (int i = 0; i < TM; i++)
                #pragma unroll
                for (int j = 0; j < TN; j++)
                    acc[i][j] += ra[i] * rb[j];
        }
        __syncthreads();
    }
    #pragma unroll
    for (int i = 0; i < TM; i++) {
        int r = row0 + ty * TM + i;
        #pragma unroll
        for (int j = 0; j < TN; j += 4) {
            int c = col0 + tx * TN + j;
            float4 v = make_float4(acc[i][j], acc[i][j + 1], acc[i][j + 2], acc[i][j + 3]);
            if (bias) {
                v.x += bias[c]; v.y += bias[c + 1];
                v.z += bias[c + 2]; v.w += bias[c + 3];
            }
            *(float4*)(C + (size_t)r * N + c) = v;
        }
    }
}

// ---------------- combine expert outputs with mask ----------------
__global__ void combine_kernel(const float* __restrict__ exp_b, int l) {
    int s = blockIdx.x;
    int o = threadIdx.x;
    float acc = 0.f;
    #pragma unroll
    for (int e = 0; e < E; e++) {
        float m = g_mask[s * E + e];
        acc += m * (g_y[(size_t)s * (E * D) + e * D + o] + exp_b[l * E * D + e * D + o]);
    }
    g_x[s * D + o] = acc;
}

// ---------------- final LayerNorm ----------------
__global__ void ln_kernel(const float* __restrict__ g, const float* __restrict__ b) {
    int s = blockIdx.x;
    int d = threadIdx.x;
    float v = g_x[s * D + d];
    __shared__ float sh[256];
    sh[d] = v;
    __syncthreads();
    for (int off = 128; off > 0; off >>= 1) {
        if (d < off) sh[d] += sh[d + off];
        __syncthreads();
    }
    float mean = sh[0] / (float)D;
    __syncthreads();
    float c = v - mean;
    sh[d] = c * c;
    __syncthreads();
    for (int off = 128; off > 0; off >>= 1) {
        if (d < off) sh[d] += sh[d + off];
        __syncthreads();
    }
    float var = sh[0] / (float)D;   // biased
    g_x[s * D + d] = c * rsqrtf(var + 1e-5f) * g[d] + b[d];
}

// ---------------- launch ----------------
extern "C" void kernel_launch(void* const* d_in, const int* in_sizes, int n_in,
                              void* d_out, int out_size) {
    const int*   tokens   = (const int*)  d_in[0];
    const float* emb      = (const float*)d_in[1];
    const float* buffers  = (const float*)d_in[2];
    const float* decays   = (const float*)d_in[3];
    const float* gate_w   = (const float*)d_in[4];
    const float* gating_W = (const float*)d_in[5];
    const float* gating_b = (const float*)d_in[6];
    const float* exp_W    = (const float*)d_in[7];
    const float* exp_b    = (const float*)d_in[8];
    const float* ln_g     = (const float*)d_in[9];
    const float* ln_b     = (const float*)d_in[10];
    const float* head_W   = (const float*)d_in[11];
    const float* head_b   = (const float*)d_in[12];
    float* out = (float*)d_out;

    float *xp, *yp;
    cudaGetSymbolAddress((void**)&xp, g_x);
    cudaGetSymbolAddress((void**)&yp, g_y);

    embed_kernel<<<S, 256>>>(tokens, emb);

    for (int l = 0; l < L; l++) {
        stats_kernel<<<D, 256>>>(buffers, decays, l);
        norm_score_kernel<<<S, 256>>>(gate_w, l);
        select_kernel<<<1, 1024>>>();
        gate_mask_kernel<<<S, 256>>>(gating_W, gating_b, l);
        dim3 grid_e((E * D) / BN, S / BM);
        sgemm_nt<<<grid_e, 256>>>(xp, exp_W + (size_t)l * E * D * D, yp,
                                  S, E * D, D, nullptr);
        combine_kernel<<<S, 256>>>(exp_b, l);
    }

    ln_kernel<<<S, 256>>>(ln_g, ln_b);

    dim3 grid_h(V / BN, S / BM);
    sgemm_nt<<<grid_h, 256>>>(xp, head_W, out, S, V, D, head_b);
}

// round 5
// speedup vs baseline: 1.7854x; 1.7854x over previous
#include <cuda_runtime.h>
#include <cuda_bf16.h>
#include <cstdint>

#define S 4096
#define D 256
#define L 4
#define E 4
#define V 32000
#define KGATE 2201   // int(4096 * sigmoid(0.15))

// ---------------- device scratch (no allocations allowed) ----------------
__device__ float g_x[S * D];            // fp32 activations
__device__ float g_y[S * E * D];        // all-expert outputs
__device__ float g_scores[S];
__device__ float g_mu[D];
__device__ float g_istd[D];
__device__ float g_absnb[D];
__device__ float g_thr[1];
__device__ float g_mask[S * E];
__device__ __nv_bfloat16 g_xs0[S * D], g_xs1[S * D];   // LN'd x limbs (head A)
__device__ __nv_bfloat16 g_wh0[V * D], g_wh1[V * D];   // head W limbs

// ================= PTX helpers (sm_80-class, legal on plain sm_103) ==========
__device__ __forceinline__ uint32_t smem_u32(const void* p) {
    uint32_t a;
    asm("{ .reg .u64 t; cvta.to.shared.u64 t, %1; cvt.u32.u64 %0, t; }" : "=r"(a) : "l"(p));
    return a;
}
__device__ __forceinline__ void cp_async16(uint32_t s, const void* g) {
    asm volatile("cp.async.cg.shared.global [%0], [%1], 16;" :: "r"(s), "l"(g));
}
__device__ __forceinline__ void cp_commit() {
    asm volatile("cp.async.commit_group;");
}
template <int N>
__device__ __forceinline__ void cp_wait() {
    asm volatile("cp.async.wait_group %0;" :: "n"(N));
}
__device__ __forceinline__ uint32_t lds32(uint32_t addr) {
    uint32_t v;
    asm volatile("ld.shared.b32 %0, [%1];" : "=r"(v) : "r"(addr));
    return v;
}
__device__ __forceinline__ void mma16816(float* c, const uint32_t* a, const uint32_t* b) {
    asm volatile("mma.sync.aligned.m16n8k16.row.col.f32.bf16.bf16.f32 "
                 "{%0,%1,%2,%3}, {%4,%5,%6,%7}, {%8,%9}, {%0,%1,%2,%3};"
                 : "+f"(c[0]), "+f"(c[1]), "+f"(c[2]), "+f"(c[3])
                 : "r"(a[0]), "r"(a[1]), "r"(a[2]), "r"(a[3]), "r"(b[0]), "r"(b[1]));
}

// =============== head GEMM: out[S,V] = X·W^T + bias, split bf16 (3 passes) ======
// X,W limbs bf16 [rows,256] row-major. CTA tile 128x128, 8 warps x (64x32).
// K-chunk 64, cp.async double buffer. Passes (0,0),(0,1),(1,0); err ~2^-18.
#define ROWB 144                        // 64 bf16 + pad = 144 bytes per smem row
#define TILEB (128 * ROWB)              // 18432 B per tile
#define HSTAGE (4 * TILEB)              // A0,A1,B0,B1 tiles per stage
__global__ __launch_bounds__(256, 1) void head_gemm(
    const __nv_bfloat16* __restrict__ A0, const __nv_bfloat16* __restrict__ A1,
    const __nv_bfloat16* __restrict__ B0, const __nv_bfloat16* __restrict__ B1,
    float* __restrict__ C, const float* __restrict__ bias)
{
    extern __shared__ char smem[];
    uint32_t sbase = smem_u32(smem);
    int tid = threadIdx.x, lane = tid & 31, wid = tid >> 5;
    int grp = lane >> 2, tig = lane & 3;
    int m_off = (wid >> 2) * 64;
    int n_off = (wid & 3) * 32;
    int row0 = blockIdx.y * 128, col0 = blockIdx.x * 128;
    const int N = V;

    float acc[4][4][4];
    #pragma unroll
    for (int i = 0; i < 4; i++)
        #pragma unroll
        for (int j = 0; j < 4; j++)
            #pragma unroll
            for (int k = 0; k < 4; k++) acc[i][j][k] = 0.f;

    // prologue: stage 0
    {
        uint32_t sb = sbase;
        #pragma unroll
        for (int i = 0; i < 4; i++) {
            int idx = tid + i * 256;
            int r = idx >> 3, c8 = idx & 7;
            uint32_t so = r * ROWB + c8 * 16;
            cp_async16(sb + 0 * TILEB + so, A0 + (size_t)(row0 + r) * 256 + c8 * 8);
            cp_async16(sb + 1 * TILEB + so, A1 + (size_t)(row0 + r) * 256 + c8 * 8);
            cp_async16(sb + 2 * TILEB + so, B0 + (size_t)(col0 + r) * 256 + c8 * 8);
            cp_async16(sb + 3 * TILEB + so, B1 + (size_t)(col0 + r) * 256 + c8 * 8);
        }
        cp_commit();
    }

    #pragma unroll
    for (int ch = 0; ch < 4; ch++) {
        // issue next stage into the other buffer
        if (ch + 1 < 4) {
            uint32_t sb = sbase + ((ch + 1) & 1) * HSTAGE;
            int k0 = (ch + 1) * 64;
            #pragma unroll
            for (int i = 0; i < 4; i++) {
                int idx = tid + i * 256;
                int r = idx >> 3, c8 = idx & 7;
                uint32_t so = r * ROWB + c8 * 16;
                cp_async16(sb + 0 * TILEB + so, A0 + (size_t)(row0 + r) * 256 + k0 + c8 * 8);
                cp_async16(sb + 1 * TILEB + so, A1 + (size_t)(row0 + r) * 256 + k0 + c8 * 8);
                cp_async16(sb + 2 * TILEB + so, B0 + (size_t)(col0 + r) * 256 + k0 + c8 * 8);
                cp_async16(sb + 3 * TILEB + so, B1 + (size_t)(col0 + r) * 256 + k0 + c8 * 8);
            }
            cp_commit();
            cp_wait<1>();      // current stage complete, next in flight
        } else {
            cp_wait<0>();
        }
        __syncthreads();

        uint32_t sb = sbase + (ch & 1) * HSTAGE;
        #pragma unroll
        for (int ks = 0; ks < 4; ks++) {
            // pass list: (a_tile, b_tile) in {(0,0),(0,1),(1,0)}
            #pragma unroll
            for (int p = 0; p < 3; p++) {
                const int ta = (p == 2) ? 1 : 0;
                const int tb = (p == 1) ? 1 : 0;
                uint32_t a[4][4];
                #pragma unroll
                for (int mt = 0; mt < 4; mt++) {
                    uint32_t base = sb + ta * TILEB
                                  + (m_off + mt * 16 + grp) * ROWB + ks * 32 + tig * 4;
                    a[mt][0] = lds32(base);
                    a[mt][1] = lds32(base + 8 * ROWB);
                    a[mt][2] = lds32(base + 16);
                    a[mt][3] = lds32(base + 8 * ROWB + 16);
                }
                uint32_t b[4][2];
                #pragma unroll
                for (int nt = 0; nt < 4; nt++) {
                    uint32_t base = sb + (2 + tb) * TILEB
                                  + (n_off + nt * 8 + grp) * ROWB + ks * 32 + tig * 4;
                    b[nt][0] = lds32(base);
                    b[nt][1] = lds32(base + 16);
                }
                #pragma unroll
                for (int mt = 0; mt < 4; mt++)
                    #pragma unroll
                    for (int nt = 0; nt < 4; nt++)
                        mma16816(acc[mt][nt], a[mt], b[nt]);
            }
        }
        __syncthreads();
    }

    // epilogue: c0,c1=(row=grp, col=2tig+{0,1}), c2,c3=row+8
    int rb = row0 + m_off + grp;
    int cb = col0 + n_off + tig * 2;
    #pragma unroll
    for (int mt = 0; mt < 4; mt++) {
        #pragma unroll
        for (int nt = 0; nt < 4; nt++) {
            int cc = cb + nt * 8;
            float b0 = bias[cc], b1 = bias[cc + 1];
            float2 v0 = make_float2(acc[mt][nt][0] + b0, acc[mt][nt][1] + b1);
            float2 v1 = make_float2(acc[mt][nt][2] + b0, acc[mt][nt][3] + b1);
            *(float2*)(C + (size_t)(rb + mt * 16) * N + cc) = v0;
            *(float2*)(C + (size_t)(rb + mt * 16 + 8) * N + cc) = v1;
        }
    }
}

// ---------------- fp32 SGEMM (verified in R1): C[M,N] = A·B^T ----------------
#define BM 128
#define BN 128
#define BK 16
#define TM 8
#define TN 8
__global__ __launch_bounds__(256) void sgemm_nt(const float* __restrict__ A,
                                                const float* __restrict__ B,
                                                float* __restrict__ C,
                                                int M, int N, int K) {
    __shared__ float As[BK][BM];
    __shared__ float Bs[BK][BN];
    int tid = threadIdx.x;
    int tx = tid & 15, ty = tid >> 4;
    int row0 = blockIdx.y * BM, col0 = blockIdx.x * BN;
    float acc[TM][TN];
    #pragma unroll
    for (int i = 0; i < TM; i++)
        #pragma unroll
        for (int j = 0; j < TN; j++) acc[i][j] = 0.f;

    for (int k0 = 0; k0 < K; k0 += BK) {
        #pragma unroll
        for (int i = 0; i < 2; i++) {
            int idx = tid + i * 256;
            int r = idx >> 2;
            int c4 = (idx & 3) << 2;
            float4 va = *(const float4*)(A + (size_t)(row0 + r) * K + k0 + c4);
            As[c4 + 0][r] = va.x; As[c4 + 1][r] = va.y;
            As[c4 + 2][r] = va.z; As[c4 + 3][r] = va.w;
            float4 vb = *(const float4*)(B + (size_t)(col0 + r) * K + k0 + c4);
            Bs[c4 + 0][r] = vb.x; Bs[c4 + 1][r] = vb.y;
            Bs[c4 + 2][r] = vb.z; Bs[c4 + 3][r] = vb.w;
        }
        __syncthreads();
        #pragma unroll
        for (int kk = 0; kk < BK; kk++) {
            float ra[TM], rb[TN];
            #pragma unroll
            for (int i = 0; i < TM; i++) ra[i] = As[kk][ty * TM + i];
            #pragma unroll
            for (int j = 0; j < TN; j++) rb[j] = Bs[kk][tx * TN + j];
            #pragma unroll
            for (int i = 0; i < TM; i++)
                #pragma unroll
                for (int j = 0; j < TN; j++)
                    acc[i][j] += ra[i] * rb[j];
        }
        __syncthreads();
    }
    #pragma unroll
    for (int i = 0; i < TM; i++) {
        int r = row0 + ty * TM + i;
        #pragma unroll
        for (int j = 0; j < TN; j += 4) {
            int c = col0 + tx * TN + j;
            float4 v = make_float4(acc[i][j], acc[i][j + 1], acc[i][j + 2], acc[i][j + 3]);
            *(float4*)(C + (size_t)r * N + c) = v;
        }
    }
}

// ---------------- head W limb split ----------------
__global__ void split2_kernel(const float* __restrict__ src,
                              __nv_bfloat16* __restrict__ h0,
                              __nv_bfloat16* __restrict__ h1, int n) {
    int i = blockIdx.x * 256 + threadIdx.x;
    if (i >= n) return;
    float v = src[i];
    __nv_bfloat16 a = __float2bfloat16(v);
    h0[i] = a;
    h1[i] = __float2bfloat16(v - __bfloat162float(a));
}

// ---------------- embedding gather ----------------
__global__ void embed_kernel(const int* __restrict__ tokens,
                             const float* __restrict__ emb) {
    int s = blockIdx.x, d = threadIdx.x;
    g_x[s * D + d] = emb[(size_t)tokens[s] * D + d];
}

// ---------------- AstroNorm column stats ----------------
__global__ void stats_kernel(const float* __restrict__ buffers,
                             const float* __restrict__ decays, int l) {
    int d = blockIdx.x, tid = threadIdx.x;
    float s = 0.f, s2 = 0.f;
    for (int i = tid; i < S; i += 256) {
        float v = g_x[i * D + d];
        s += v; s2 += v * v;
    }
    __shared__ float sh[256], sh2[256];
    sh[tid] = s; sh2[tid] = s2;
    __syncthreads();
    for (int off = 128; off > 0; off >>= 1) {
        if (tid < off) { sh[tid] += sh[tid + off]; sh2[tid] += sh2[tid + off]; }
        __syncthreads();
    }
    if (tid == 0) {
        float mu = sh[0] / (float)S;
        float var = (sh2[0] - (float)S * mu * mu) / (float)(S - 1);
        g_mu[d] = mu;
        g_istd[d] = rsqrtf(var + 1e-6f);
        float dec = decays[l];
        float nb = dec * buffers[l * D + d] + (1.f - dec) * mu;
        g_absnb[d] = fabsf(nb);
    }
}

// ---------------- apply AstroNorm + gate scores ----------------
__global__ void norm_score_kernel(const float* __restrict__ gate_w, int l) {
    int s = blockIdx.x, d = threadIdx.x;
    float v = g_x[s * D + d];
    float mu = g_mu[d];
    float v2 = (fabsf(v - mu) > g_absnb[d] ? mu : v) * g_istd[d];
    g_x[s * D + d] = v2;
    __shared__ float sh[256];
    sh[d] = v2 * gate_w[l * D + d];
    __syncthreads();
    for (int off = 128; off > 0; off >>= 1) {
        if (d < off) sh[d] += sh[d + off];
        __syncthreads();
    }
    if (d == 0) g_scores[s] = sh[0];
}

// ---------------- k-th largest: brute-force order statistic ----------------
__global__ void select_kernel() {
    __shared__ float sc[S];
    int tid = threadIdx.x;                       // 256
    for (int i = tid; i < S; i += 256) sc[i] = g_scores[i];
    __syncthreads();
    int i = blockIdx.x * 256 + tid;              // grid 16 -> 4096 threads
    float v = sc[i];
    int gt = 0, ge = 0;
    #pragma unroll 8
    for (int j = 0; j < S; j++) {
        float u = sc[j];
        gt += (u > v);
        ge += (u >= v);
    }
    if (gt < KGATE && ge >= KGATE) g_thr[0] = v;
}

// ---------------- sparsity gate + expert routing mask (R1-verified) ----------------
__global__ void gate_mask_kernel(const float* __restrict__ gating_W,
                                 const float* __restrict__ gating_b, int l) {
    int s = blockIdx.x, d = threadIdx.x;
    bool keep = g_scores[s] > g_thr[0];
    float v = keep ? g_x[s * D + d] : 0.f;
    g_x[s * D + d] = v;
    __shared__ float sh[256];
    __shared__ float gs[E];
    #pragma unroll
    for (int e = 0; e < E; e++) {
        sh[d] = v * gating_W[l * E * D + e * D + d];
        __syncthreads();
        for (int off = 128; off > 0; off >>= 1) {
            if (d < off) sh[d] += sh[d + off];
            __syncthreads();
        }
        if (d == 0) gs[e] = sh[0] + gating_b[l * E + e];
        __syncthreads();
    }
    if (d == 0) {
        float best = gs[0]; int excl = 0;
        #pragma unroll
        for (int e = 1; e < E; e++)
            if (gs[e] <= best) { best = gs[e]; excl = e; }
        #pragma unroll
        for (int e = 0; e < E; e++)
            g_mask[s * E + e] = (e == excl) ? 0.f : 1.f;
    }
}

// ---------------- combine expert outputs with mask ----------------
__global__ void combine_kernel(const float* __restrict__ exp_b, int l) {
    int s = blockIdx.x, o = threadIdx.x;
    float acc = 0.f;
    #pragma unroll
    for (int e = 0; e < E; e++) {
        float m = g_mask[s * E + e];
        acc += m * (g_y[(size_t)s * (E * D) + e * D + o] + exp_b[l * E * D + e * D + o]);
    }
    g_x[s * D + o] = acc;
}

// ---------------- final LayerNorm + 2-limb split for head ----------------
__global__ void ln_kernel(const float* __restrict__ g, const float* __restrict__ b) {
    int s = blockIdx.x, d = threadIdx.x;
    float v = g_x[s * D + d];
    __shared__ float sh[256];
    sh[d] = v;
    __syncthreads();
    for (int off = 128; off > 0; off >>= 1) {
        if (d < off) sh[d] += sh[d + off];
        __syncthreads();
    }
    float mean = sh[0] / (float)D;
    __syncthreads();
    float c = v - mean;
    sh[d] = c * c;
    __syncthreads();
    for (int off = 128; off > 0; off >>= 1) {
        if (d < off) sh[d] += sh[d + off];
        __syncthreads();
    }
    float var = sh[0] / (float)D;
    float y = c * rsqrtf(var + 1e-5f) * g[d] + b[d];
    __nv_bfloat16 h = __float2bfloat16(y);
    g_xs0[s * D + d] = h;
    g_xs1[s * D + d] = __float2bfloat16(y - __bfloat162float(h));
}

// ---------------- launch ----------------
extern "C" void kernel_launch(void* const* d_in, const int* in_sizes, int n_in,
                              void* d_out, int out_size) {
    const int*   tokens   = (const int*)  d_in[0];
    const float* emb      = (const float*)d_in[1];
    const float* buffers  = (const float*)d_in[2];
    const float* decays   = (const float*)d_in[3];
    const float* gate_w   = (const float*)d_in[4];
    const float* gating_W = (const float*)d_in[5];
    const float* gating_b = (const float*)d_in[6];
    const float* exp_W    = (const float*)d_in[7];
    const float* exp_b    = (const float*)d_in[8];
    const float* ln_g     = (const float*)d_in[9];
    const float* ln_b     = (const float*)d_in[10];
    const float* head_W   = (const float*)d_in[11];
    const float* head_b   = (const float*)d_in[12];
    float* out = (float*)d_out;

    float *xp, *yp;
    cudaGetSymbolAddress((void**)&xp, g_x);
    cudaGetSymbolAddress((void**)&yp, g_y);
    __nv_bfloat16 *xs0, *xs1, *wh0, *wh1;
    cudaGetSymbolAddress((void**)&xs0, g_xs0);
    cudaGetSymbolAddress((void**)&xs1, g_xs1);
    cudaGetSymbolAddress((void**)&wh0, g_wh0);
    cudaGetSymbolAddress((void**)&wh1, g_wh1);

    const int SMEMH = 2 * HSTAGE;   // 147456
    cudaFuncSetAttribute(head_gemm, cudaFuncAttributeMaxDynamicSharedMemorySize, SMEMH);

    // head W limb split (every call; deterministic)
    split2_kernel<<<(V * D + 255) / 256, 256>>>(head_W, wh0, wh1, V * D);

    embed_kernel<<<S, 256>>>(tokens, emb);

    for (int l = 0; l < L; l++) {
        stats_kernel<<<D, 256>>>(buffers, decays, l);
        norm_score_kernel<<<S, 256>>>(gate_w, l);
        select_kernel<<<16, 256>>>();
        gate_mask_kernel<<<S, 256>>>(gating_W, gating_b, l);
        dim3 ge((E * D) / BN, S / BM);   // (8, 32)
        sgemm_nt<<<ge, 256>>>(xp, exp_W + (size_t)l * E * D * D, yp, S, E * D, D);
        combine_kernel<<<S, 256>>>(exp_b, l);
    }

    ln_kernel<<<S, 256>>>(ln_g, ln_b);

    dim3 gh(V / 128, S / 128);           // (250, 32)
    head_gemm<<<gh, 256, SMEMH>>>(xs0, xs1, wh0, wh1, out, head_b);
}

// round 6
// speedup vs baseline: 1.9950x; 1.1174x over previous
#include <cuda_runtime.h>
#include <cuda_bf16.h>
#include <cstdint>

#define S 4096
#define D 256
#define L 4
#define E 4
#define V 32000
#define KGATE 2201   // int(4096 * sigmoid(0.15))

// ---------------- device scratch (no allocations allowed) ----------------
__device__ float g_x[S * D];            // fp32 activations
__device__ float g_y[S * E * D];        // all-expert outputs
__device__ float g_scores[S];
__device__ float g_mu[D];
__device__ float g_istd[D];
__device__ float g_absnb[D];
__device__ float g_thr[1];
__device__ float g_mask[S * E];
__device__ __nv_bfloat16 g_xs0[S * D], g_xs1[S * D];   // LN'd x limbs (head A)
__device__ __nv_bfloat16 g_wh0[V * D], g_wh1[V * D];   // head W limbs

// ================= PTX helpers (sm_80-class, legal on plain sm_103) ==========
__device__ __forceinline__ uint32_t smem_u32(const void* p) {
    uint32_t a;
    asm("{ .reg .u64 t; cvta.to.shared.u64 t, %1; cvt.u32.u64 %0, t; }" : "=r"(a) : "l"(p));
    return a;
}
__device__ __forceinline__ void cp_async16(uint32_t s, const void* g) {
    asm volatile("cp.async.cg.shared.global [%0], [%1], 16;" :: "r"(s), "l"(g));
}
__device__ __forceinline__ void cp_commit() {
    asm volatile("cp.async.commit_group;");
}
template <int N>
__device__ __forceinline__ void cp_wait() {
    asm volatile("cp.async.wait_group %0;" :: "n"(N));
}
__device__ __forceinline__ uint32_t lds32(uint32_t addr) {
    uint32_t v;
    asm volatile("ld.shared.b32 %0, [%1];" : "=r"(v) : "r"(addr));
    return v;
}
__device__ __forceinline__ void mma16816(float* c, const uint32_t* a, const uint32_t* b) {
    asm volatile("mma.sync.aligned.m16n8k16.row.col.f32.bf16.bf16.f32 "
                 "{%0,%1,%2,%3}, {%4,%5,%6,%7}, {%8,%9}, {%0,%1,%2,%3};"
                 : "+f"(c[0]), "+f"(c[1]), "+f"(c[2]), "+f"(c[3])
                 : "r"(a[0]), "r"(a[1]), "r"(a[2]), "r"(a[3]), "r"(b[0]), "r"(b[1]));
}

// =============== head GEMM: out[S,V] = X·W^T + bias, split bf16 (3 passes) ======
// CTA tile 128x256, 8 warps x (64x64). K-chunk 64, double-buffered cp.async.
// Limb passes (a,b) in {(0,0),(0,1),(1,0)}; err ~2^-18 (bounded, no feedback).
#define ROWB 144                        // 64 bf16 + pad = 144 B per smem row
#define ATILE (128 * ROWB)              // 18432 B
#define BTILE (256 * ROWB)              // 36864 B
#define HSTAGE (2 * ATILE + 2 * BTILE)  // 110592 B per stage
__global__ __launch_bounds__(256, 1) void head_gemm(
    const __nv_bfloat16* __restrict__ A0, const __nv_bfloat16* __restrict__ A1,
    const __nv_bfloat16* __restrict__ B0, const __nv_bfloat16* __restrict__ B1,
    float* __restrict__ C, const float* __restrict__ bias)
{
    extern __shared__ char smem[];
    uint32_t sbase = smem_u32(smem);
    int tid = threadIdx.x, lane = tid & 31, wid = tid >> 5;
    int grp = lane >> 2, tig = lane & 3;
    int m_off = (wid >> 2) * 64;         // 2 warp rows x 64
    int n_off = (wid & 3) * 64;          // 4 warp cols x 64
    int row0 = blockIdx.y * 128, col0 = blockIdx.x * 256;
    const int N = V;
    const __nv_bfloat16* Ap[2] = {A0, A1};
    const __nv_bfloat16* Bp[2] = {B0, B1};

    float acc[4][8][4];
    #pragma unroll
    for (int i = 0; i < 4; i++)
        #pragma unroll
        for (int j = 0; j < 8; j++)
            #pragma unroll
            for (int k = 0; k < 4; k++) acc[i][j][k] = 0.f;

    // ---- stage loader ----
    auto load_stage = [&](int ch) {
        uint32_t sb = sbase + (ch & 1) * HSTAGE;
        int k0 = ch * 64;
        // A: 2 limbs x 128 rows x 8 chunks = 2048 -> 8 per thread
        #pragma unroll
        for (int i = 0; i < 8; i++) {
            int idx = tid + i * 256;
            int r = idx >> 3, c8 = idx & 7;          // r: limb*128+row
            int limb = r >> 7, row = r & 127;
            uint32_t so = limb * ATILE + row * ROWB + c8 * 16;
            cp_async16(sb + so, Ap[limb] + (size_t)(row0 + row) * 256 + k0 + c8 * 8);
        }
        // B: 2 limbs x 256 rows x 8 chunks = 4096 -> 16 per thread
        #pragma unroll
        for (int i = 0; i < 16; i++) {
            int idx = tid + i * 256;
            int r = idx >> 3, c8 = idx & 7;          // r: limb*256+row
            int limb = r >> 8, row = r & 255;
            uint32_t so = 2 * ATILE + limb * BTILE + row * ROWB + c8 * 16;
            cp_async16(sb + so, Bp[limb] + (size_t)(col0 + row) * 256 + k0 + c8 * 8);
        }
    };

    load_stage(0); cp_commit();

    #pragma unroll
    for (int ch = 0; ch < 4; ch++) {
        if (ch + 1 < 4) { load_stage(ch + 1); cp_commit(); cp_wait<1>(); }
        else           { cp_wait<0>(); }
        __syncthreads();

        uint32_t sb = sbase + (ch & 1) * HSTAGE;
        #pragma unroll
        for (int ks = 0; ks < 4; ks++) {
            #pragma unroll
            for (int p = 0; p < 3; p++) {
                const int ta = (p == 2) ? 1 : 0;
                const int tb = (p == 1) ? 1 : 0;
                // A fragments: a0=(row=grp,k=2tig) a1=row+8 a2=k+8 a3=both
                uint32_t a[4][4];
                #pragma unroll
                for (int mt = 0; mt < 4; mt++) {
                    uint32_t base = sb + ta * ATILE
                                  + (m_off + mt * 16 + grp) * ROWB + ks * 32 + tig * 4;
                    a[mt][0] = lds32(base);
                    a[mt][1] = lds32(base + 8 * ROWB);
                    a[mt][2] = lds32(base + 16);
                    a[mt][3] = lds32(base + 8 * ROWB + 16);
                }
                #pragma unroll
                for (int nt = 0; nt < 8; nt++) {
                    // B fragments: b0=(k=2tig,n=grp) b1=(k+8)
                    uint32_t base = sb + 2 * ATILE + tb * BTILE
                                  + (n_off + nt * 8 + grp) * ROWB + ks * 32 + tig * 4;
                    uint32_t b[2];
                    b[0] = lds32(base);
                    b[1] = lds32(base + 16);
                    #pragma unroll
                    for (int mt = 0; mt < 4; mt++)
                        mma16816(acc[mt][nt], a[mt], b);
                }
            }
        }
        __syncthreads();
    }

    // epilogue: c0,c1=(row=grp, col=2tig+{0,1}), c2,c3=row+8
    int rb = row0 + m_off + grp;
    int cb = col0 + n_off + tig * 2;
    #pragma unroll
    for (int mt = 0; mt < 4; mt++) {
        #pragma unroll
        for (int nt = 0; nt < 8; nt++) {
            int cc = cb + nt * 8;
            float b0 = bias[cc], b1 = bias[cc + 1];
            float2 v0 = make_float2(acc[mt][nt][0] + b0, acc[mt][nt][1] + b1);
            float2 v1 = make_float2(acc[mt][nt][2] + b0, acc[mt][nt][3] + b1);
            *(float2*)(C + (size_t)(rb + mt * 16) * N + cc) = v0;
            *(float2*)(C + (size_t)(rb + mt * 16 + 8) * N + cc) = v1;
        }
    }
}

// ---------------- fp32 SGEMM (verified): C[M,N] = A·B^T ----------------
#define BM 128
#define BN 128
#define BK 16
#define TM 8
#define TN 8
__global__ __launch_bounds__(256) void sgemm_nt(const float* __restrict__ A,
                                                const float* __restrict__ B,
                                                float* __restrict__ C,
                                                int M, int N, int K) {
    __shared__ float As[BK][BM];
    __shared__ float Bs[BK][BN];
    int tid = threadIdx.x;
    int tx = tid & 15, ty = tid >> 4;
    int row0 = blockIdx.y * BM, col0 = blockIdx.x * BN;
    float acc[TM][TN];
    #pragma unroll
    for (int i = 0; i < TM; i++)
        #pragma unroll
        for (int j = 0; j < TN; j++) acc[i][j] = 0.f;

    for (int k0 = 0; k0 < K; k0 += BK) {
        #pragma unroll
        for (int i = 0; i < 2; i++) {
            int idx = tid + i * 256;
            int r = idx >> 2;
            int c4 = (idx & 3) << 2;
            float4 va = *(const float4*)(A + (size_t)(row0 + r) * K + k0 + c4);
            As[c4 + 0][r] = va.x; As[c4 + 1][r] = va.y;
            As[c4 + 2][r] = va.z; As[c4 + 3][r] = va.w;
            float4 vb = *(const float4*)(B + (size_t)(col0 + r) * K + k0 + c4);
            Bs[c4 + 0][r] = vb.x; Bs[c4 + 1][r] = vb.y;
            Bs[c4 + 2][r] = vb.z; Bs[c4 + 3][r] = vb.w;
        }
        __syncthreads();
        #pragma unroll
        for (int kk = 0; kk < BK; kk++) {
            float ra[TM], rb[TN];
            #pragma unroll
            for (int i = 0; i < TM; i++) ra[i] = As[kk][ty * TM + i];
            #pragma unroll
            for (int j = 0; j < TN; j++) rb[j] = Bs[kk][tx * TN + j];
            #pragma unroll
            for (int i = 0; i < TM; i++)
                #pragma unroll
                for (int j = 0; j < TN; j++)
                    acc[i][j] += ra[i] * rb[j];
        }
        __syncthreads();
    }
    #pragma unroll
    for (int i = 0; i < TM; i++) {
        int r = row0 + ty * TM + i;
        #pragma unroll
        for (int j = 0; j < TN; j += 4) {
            int c = col0 + tx * TN + j;
            float4 v = make_float4(acc[i][j], acc[i][j + 1], acc[i][j + 2], acc[i][j + 3]);
            *(float4*)(C + (size_t)r * N + c) = v;
        }
    }
}

// ---------------- head W limb split ----------------
__global__ void split2_kernel(const float* __restrict__ src,
                              __nv_bfloat16* __restrict__ h0,
                              __nv_bfloat16* __restrict__ h1, int n) {
    int i = blockIdx.x * 256 + threadIdx.x;
    if (i >= n) return;
    float v = src[i];
    __nv_bfloat16 a = __float2bfloat16(v);
    h0[i] = a;
    h1[i] = __float2bfloat16(v - __bfloat162float(a));
}

// ---------------- embedding gather ----------------
__global__ void embed_kernel(const int* __restrict__ tokens,
                             const float* __restrict__ emb) {
    int s = blockIdx.x, d = threadIdx.x;
    g_x[s * D + d] = emb[(size_t)tokens[s] * D + d];
}

// ---------------- AstroNorm column stats ----------------
__global__ void stats_kernel(const float* __restrict__ buffers,
                             const float* __restrict__ decays, int l) {
    int d = blockIdx.x, tid = threadIdx.x;
    float s = 0.f, s2 = 0.f;
    for (int i = tid; i < S; i += 256) {
        float v = g_x[i * D + d];
        s += v; s2 += v * v;
    }
    __shared__ float sh[256], sh2[256];
    sh[tid] = s; sh2[tid] = s2;
    __syncthreads();
    for (int off = 128; off > 0; off >>= 1) {
        if (tid < off) { sh[tid] += sh[tid + off]; sh2[tid] += sh2[tid + off]; }
        __syncthreads();
    }
    if (tid == 0) {
        float mu = sh[0] / (float)S;
        float var = (sh2[0] - (float)S * mu * mu) / (float)(S - 1);
        g_mu[d] = mu;
        g_istd[d] = rsqrtf(var + 1e-6f);
        float dec = decays[l];
        float nb = dec * buffers[l * D + d] + (1.f - dec) * mu;
        g_absnb[d] = fabsf(nb);
    }
}

// ---------------- apply AstroNorm + gate scores ----------------
__global__ void norm_score_kernel(const float* __restrict__ gate_w, int l) {
    int s = blockIdx.x, d = threadIdx.x;
    float v = g_x[s * D + d];
    float mu = g_mu[d];
    float v2 = (fabsf(v - mu) > g_absnb[d] ? mu : v) * g_istd[d];
    g_x[s * D + d] = v2;
    __shared__ float sh[256];
    sh[d] = v2 * gate_w[l * D + d];
    __syncthreads();
    for (int off = 128; off > 0; off >>= 1) {
        if (d < off) sh[d] += sh[d + off];
        __syncthreads();
    }
    if (d == 0) g_scores[s] = sh[0];
}

// ---------------- k-th largest: parallel order statistic ----------------
// grid 128 x 256. Block b: candidates b*32..b*32+31; 8 threads per candidate
// each scan a 512-slice. v is k-th largest iff gt < K <= ge; tie writers
// store identical bits -> deterministic.
__global__ void select_kernel() {
    __shared__ float sc[S];
    __shared__ int sgt[32][8], sge[32][8];
    int tid = threadIdx.x;
    for (int i = tid; i < S; i += 256) sc[i] = g_scores[i];
    __syncthreads();
    int c = tid >> 3, part = tid & 7;
    float v = sc[blockIdx.x * 32 + c];
    int gt = 0, ge = 0;
    int j0 = part * 512;
    #pragma unroll 8
    for (int j = j0; j < j0 + 512; j++) {
        float u = sc[j];
        gt += (u > v);
        ge += (u >= v);
    }
    sgt[c][part] = gt; sge[c][part] = ge;
    __syncthreads();
    if (part == 0) {
        int GT = 0, GE = 0;
        #pragma unroll
        for (int p = 0; p < 8; p++) { GT += sgt[c][p]; GE += sge[c][p]; }
        if (GT < KGATE && GE >= KGATE) g_thr[0] = v;
    }
}

// ---------------- sparsity gate + expert routing mask ----------------
__global__ void gate_mask_kernel(const float* __restrict__ gating_W,
                                 const float* __restrict__ gating_b, int l) {
    int s = blockIdx.x, d = threadIdx.x;
    bool keep = g_scores[s] > g_thr[0];
    float v = keep ? g_x[s * D + d] : 0.f;
    g_x[s * D + d] = v;
    __shared__ float sh[256];
    __shared__ float gs[E];
    #pragma unroll
    for (int e = 0; e < E; e++) {
        sh[d] = v * gating_W[l * E * D + e * D + d];
        __syncthreads();
        for (int off = 128; off > 0; off >>= 1) {
            if (d < off) sh[d] += sh[d + off];
            __syncthreads();
        }
        if (d == 0) gs[e] = sh[0] + gating_b[l * E + e];
        __syncthreads();
    }
    if (d == 0) {
        float best = gs[0]; int excl = 0;
        #pragma unroll
        for (int e = 1; e < E; e++)
            if (gs[e] <= best) { best = gs[e]; excl = e; }
        #pragma unroll
        for (int e = 0; e < E; e++)
            g_mask[s * E + e] = (e == excl) ? 0.f : 1.f;
    }
}

// ---------------- combine expert outputs with mask ----------------
__global__ void combine_kernel(const float* __restrict__ exp_b, int l) {
    int s = blockIdx.x, o = threadIdx.x;
    float acc = 0.f;
    #pragma unroll
    for (int e = 0; e < E; e++) {
        float m = g_mask[s * E + e];
        acc += m * (g_y[(size_t)s * (E * D) + e * D + o] + exp_b[l * E * D + e * D + o]);
    }
    g_x[s * D + o] = acc;
}

// ---------------- final LayerNorm + 2-limb split for head ----------------
__global__ void ln_kernel(const float* __restrict__ g, const float* __restrict__ b) {
    int s = blockIdx.x, d = threadIdx.x;
    float v = g_x[s * D + d];
    __shared__ float sh[256];
    sh[d] = v;
    __syncthreads();
    for (int off = 128; off > 0; off >>= 1) {
        if (d < off) sh[d] += sh[d + off];
        __syncthreads();
    }
    float mean = sh[0] / (float)D;
    __syncthreads();
    float c = v - mean;
    sh[d] = c * c;
    __syncthreads();
    for (int off = 128; off > 0; off >>= 1) {
        if (d < off) sh[d] += sh[d + off];
        __syncthreads();
    }
    float var = sh[0] / (float)D;
    float y = c * rsqrtf(var + 1e-5f) * g[d] + b[d];
    __nv_bfloat16 h = __float2bfloat16(y);
    g_xs0[s * D + d] = h;
    g_xs1[s * D + d] = __float2bfloat16(y - __bfloat162float(h));
}

// ---------------- launch ----------------
extern "C" void kernel_launch(void* const* d_in, const int* in_sizes, int n_in,
                              void* d_out, int out_size) {
    const int*   tokens   = (const int*)  d_in[0];
    const float* emb      = (const float*)d_in[1];
    const float* buffers  = (const float*)d_in[2];
    const float* decays   = (const float*)d_in[3];
    const float* gate_w   = (const float*)d_in[4];
    const float* gating_W = (const float*)d_in[5];
    const float* gating_b = (const float*)d_in[6];
    const float* exp_W    = (const float*)d_in[7];
    const float* exp_b    = (const float*)d_in[8];
    const float* ln_g     = (const float*)d_in[9];
    const float* ln_b     = (const float*)d_in[10];
    const float* head_W   = (const float*)d_in[11];
    const float* head_b   = (const float*)d_in[12];
    float* out = (float*)d_out;

    float *xp, *yp;
    cudaGetSymbolAddress((void**)&xp, g_x);
    cudaGetSymbolAddress((void**)&yp, g_y);
    __nv_bfloat16 *xs0, *xs1, *wh0, *wh1;
    cudaGetSymbolAddress((void**)&xs0, g_xs0);
    cudaGetSymbolAddress((void**)&xs1, g_xs1);
    cudaGetSymbolAddress((void**)&wh0, g_wh0);
    cudaGetSymbolAddress((void**)&wh1, g_wh1);

    const int SMEMH = 2 * HSTAGE;   // 221184
    cudaFuncSetAttribute(head_gemm, cudaFuncAttributeMaxDynamicSharedMemorySize, SMEMH);

    // head W limb split (every call; deterministic)
    split2_kernel<<<(V * D + 255) / 256, 256>>>(head_W, wh0, wh1, V * D);

    embed_kernel<<<S, 256>>>(tokens, emb);

    for (int l = 0; l < L; l++) {
        stats_kernel<<<D, 256>>>(buffers, decays, l);
        norm_score_kernel<<<S, 256>>>(gate_w, l);
        select_kernel<<<128, 256>>>();
        gate_mask_kernel<<<S, 256>>>(gating_W, gating_b, l);
        dim3 ge((E * D) / BN, S / BM);   // (8, 32)
        sgemm_nt<<<ge, 256>>>(xp, exp_W + (size_t)l * E * D * D, yp, S, E * D, D);
        combine_kernel<<<S, 256>>>(exp_b, l);
    }

    ln_kernel<<<S, 256>>>(ln_g, ln_b);

    dim3 gh(V / 256, S / 128);           // (125, 32)
    head_gemm<<<gh, 256, SMEMH>>>(xs0, xs1, wh0, wh1, out, head_b);
}

// round 8
// speedup vs baseline: 2.0793x; 1.0423x over previous
#include <cuda_runtime.h>
#include <cuda_bf16.h>
#include <cstdint>

#define S 4096
#define D 256
#define L 4
#define E 4
#define V 32000
#define KGATE 2201   // int(4096 * sigmoid(0.15))

// ---------------- device scratch (no allocations allowed) ----------------
__device__ float g_x[S * D];            // fp32 activations
__device__ float g_y[S * E * D];        // all-expert outputs
__device__ float g_scores[S];
__device__ float g_mu[D];
__device__ float g_istd[D];
__device__ float g_absnb[D];
__device__ float g_thr[1];
__device__ float g_mask[S * E];
__device__ __nv_bfloat16 g_xs0[S * D], g_xs1[S * D];   // LN'd x limbs (head A)
__device__ __nv_bfloat16 g_wh0[V * D], g_wh1[V * D];   // head W limbs

// ================= PTX helpers (sm_80-class, legal on plain sm_103) ==========
__device__ __forceinline__ uint32_t smem_u32(const void* p) {
    uint32_t a;
    asm("{ .reg .u64 t; cvta.to.shared.u64 t, %1; cvt.u32.u64 %0, t; }" : "=r"(a) : "l"(p));
    return a;
}
__device__ __forceinline__ void cp_async16(uint32_t s, const void* g) {
    asm volatile("cp.async.cg.shared.global [%0], [%1], 16;" :: "r"(s), "l"(g));
}
__device__ __forceinline__ void cp_commit() {
    asm volatile("cp.async.commit_group;");
}
template <int N>
__device__ __forceinline__ void cp_wait() {
    asm volatile("cp.async.wait_group %0;" :: "n"(N));
}
__device__ __forceinline__ uint32_t lds32(uint32_t addr) {
    uint32_t v;
    asm volatile("ld.shared.b32 %0, [%1];" : "=r"(v) : "r"(addr));
    return v;
}
__device__ __forceinline__ void mma16816(float* c, const uint32_t* a, const uint32_t* b) {
    asm volatile("mma.sync.aligned.m16n8k16.row.col.f32.bf16.bf16.f32 "
                 "{%0,%1,%2,%3}, {%4,%5,%6,%7}, {%8,%9}, {%0,%1,%2,%3};"
                 : "+f"(c[0]), "+f"(c[1]), "+f"(c[2]), "+f"(c[3])
                 : "r"(a[0]), "r"(a[1]), "r"(a[2]), "r"(a[3]), "r"(b[0]), "r"(b[1]));
}

// =============== head GEMM (PROVEN): out[S,V] = X·W^T + bias, 3 limb passes =====
#define ROWB 144                        // 64 bf16 + pad = 144 B per smem row
#define ATILE (128 * ROWB)              // 18432 B
#define BTILE (256 * ROWB)              // 36864 B
#define HSTAGE (2 * ATILE + 2 * BTILE)  // 110592 B per stage
__global__ __launch_bounds__(256, 1) void head_gemm(
    const __nv_bfloat16* __restrict__ A0, const __nv_bfloat16* __restrict__ A1,
    const __nv_bfloat16* __restrict__ B0, const __nv_bfloat16* __restrict__ B1,
    float* __restrict__ C, const float* __restrict__ bias)
{
    extern __shared__ char smem[];
    uint32_t sbase = smem_u32(smem);
    int tid = threadIdx.x, lane = tid & 31, wid = tid >> 5;
    int grp = lane >> 2, tig = lane & 3;
    int m_off = (wid >> 2) * 64;
    int n_off = (wid & 3) * 64;
    int row0 = blockIdx.y * 128, col0 = blockIdx.x * 256;
    const int N = V;
    const __nv_bfloat16* Ap[2] = {A0, A1};
    const __nv_bfloat16* Bp[2] = {B0, B1};

    float acc[4][8][4];
    #pragma unroll
    for (int i = 0; i < 4; i++)
        #pragma unroll
        for (int j = 0; j < 8; j++)
            #pragma unroll
            for (int k = 0; k < 4; k++) acc[i][j][k] = 0.f;

    auto load_stage = [&](int ch) {
        uint32_t sb = sbase + (ch & 1) * HSTAGE;
        int k0 = ch * 64;
        #pragma unroll
        for (int i = 0; i < 8; i++) {
            int idx = tid + i * 256;
            int r = idx >> 3, c8 = idx & 7;
            int limb = r >> 7, row = r & 127;
            uint32_t so = limb * ATILE + row * ROWB + c8 * 16;
            cp_async16(sb + so, Ap[limb] + (size_t)(row0 + row) * 256 + k0 + c8 * 8);
        }
        #pragma unroll
        for (int i = 0; i < 16; i++) {
            int idx = tid + i * 256;
            int r = idx >> 3, c8 = idx & 7;
            int limb = r >> 8, row = r & 255;
            uint32_t so = 2 * ATILE + limb * BTILE + row * ROWB + c8 * 16;
            cp_async16(sb + so, Bp[limb] + (size_t)(col0 + row) * 256 + k0 + c8 * 8);
        }
    };

    load_stage(0); cp_commit();

    #pragma unroll
    for (int ch = 0; ch < 4; ch++) {
        if (ch + 1 < 4) { load_stage(ch + 1); cp_commit(); cp_wait<1>(); }
        else           { cp_wait<0>(); }
        __syncthreads();

        uint32_t sb = sbase + (ch & 1) * HSTAGE;
        #pragma unroll
        for (int ks = 0; ks < 4; ks++) {
            #pragma unroll
            for (int p = 0; p < 3; p++) {
                const int ta = (p == 2) ? 1 : 0;
                const int tb = (p == 1) ? 1 : 0;
                uint32_t a[4][4];
                #pragma unroll
                for (int mt = 0; mt < 4; mt++) {
                    uint32_t base = sb + ta * ATILE
                                  + (m_off + mt * 16 + grp) * ROWB + ks * 32 + tig * 4;
                    a[mt][0] = lds32(base);
                    a[mt][1] = lds32(base + 8 * ROWB);
                    a[mt][2] = lds32(base + 16);
                    a[mt][3] = lds32(base + 8 * ROWB + 16);
                }
                #pragma unroll
                for (int nt = 0; nt < 8; nt++) {
                    uint32_t base = sb + 2 * ATILE + tb * BTILE
                                  + (n_off + nt * 8 + grp) * ROWB + ks * 32 + tig * 4;
                    uint32_t b[2];
                    b[0] = lds32(base);
                    b[1] = lds32(base + 16);
                    #pragma unroll
                    for (int mt = 0; mt < 4; mt++)
                        mma16816(acc[mt][nt], a[mt], b);
                }
            }
        }
        __syncthreads();
    }

    int rb = row0 + m_off + grp;
    int cb = col0 + n_off + tig * 2;
    #pragma unroll
    for (int mt = 0; mt < 4; mt++) {
        #pragma unroll
        for (int nt = 0; nt < 8; nt++) {
            int cc = cb + nt * 8;
            float b0 = bias[cc], b1 = bias[cc + 1];
            float2 v0 = make_float2(acc[mt][nt][0] + b0, acc[mt][nt][1] + b1);
            float2 v1 = make_float2(acc[mt][nt][2] + b0, acc[mt][nt][3] + b1);
            *(float2*)(C + (size_t)(rb + mt * 16) * N + cc) = v0;
            *(float2*)(C + (size_t)(rb + mt * 16 + 8) * N + cc) = v1;
        }
    }
}

// ---------------- fp32 SGEMM (proven): C[M,N] = A·B^T ----------------
#define BM 128
#define BN 128
#define BK 16
#define TM 8
#define TN 8
__global__ __launch_bounds__(256) void sgemm_nt(const float* __restrict__ A,
                                                const float* __restrict__ B,
                                                float* __restrict__ C,
                                                int M, int N, int K) {
    __shared__ float As[BK][BM];
    __shared__ float Bs[BK][BN];
    int tid = threadIdx.x;
    int tx = tid & 15, ty = tid >> 4;
    int row0 = blockIdx.y * BM, col0 = blockIdx.x * BN;
    float acc[TM][TN];
    #pragma unroll
    for (int i = 0; i < TM; i++)
        #pragma unroll
        for (int j = 0; j < TN; j++) acc[i][j] = 0.f;

    for (int k0 = 0; k0 < K; k0 += BK) {
        #pragma unroll
        for (int i = 0; i < 2; i++) {
            int idx = tid + i * 256;
            int r = idx >> 2;
            int c4 = (idx & 3) << 2;
            float4 va = *(const float4*)(A + (size_t)(row0 + r) * K + k0 + c4);
            As[c4 + 0][r] = va.x; As[c4 + 1][r] = va.y;
            As[c4 + 2][r] = va.z; As[c4 + 3][r] = va.w;
            float4 vb = *(const float4*)(B + (size_t)(col0 + r) * K + k0 + c4);
            Bs[c4 + 0][r] = vb.x; Bs[c4 + 1][r] = vb.y;
            Bs[c4 + 2][r] = vb.z; Bs[c4 + 3][r] = vb.w;
        }
        __syncthreads();
        #pragma unroll
        for (int kk = 0; kk < BK; kk++) {
            float ra[TM], rb[TN];
            #pragma unroll
            for (int i = 0; i < TM; i++) ra[i] = As[kk][ty * TM + i];
            #pragma unroll
            for (int j = 0; j < TN; j++) rb[j] = Bs[kk][tx * TN + j];
            #pragma unroll
            for (int i = 0; i < TM; i++)
                #pragma unroll
                for (int j = 0; j < TN; j++)
                    acc[i][j] += ra[i] * rb[j];
        }
        __syncthreads();
    }
    #pragma unroll
    for (int i = 0; i < TM; i++) {
        int r = row0 + ty * TM + i;
        #pragma unroll
        for (int j = 0; j < TN; j += 4) {
            int c = col0 + tx * TN + j;
            float4 v = make_float4(acc[i][j], acc[i][j + 1], acc[i][j + 2], acc[i][j + 3]);
            *(float4*)(C + (size_t)r * N + c) = v;
        }
    }
}

// ---------------- head W limb split ----------------
__global__ void split2_kernel(const float* __restrict__ src,
                              __nv_bfloat16* __restrict__ h0,
                              __nv_bfloat16* __restrict__ h1, int n) {
    int i = blockIdx.x * 256 + threadIdx.x;
    if (i >= n) return;
    float v = src[i];
    __nv_bfloat16 a = __float2bfloat16(v);
    h0[i] = a;
    h1[i] = __float2bfloat16(v - __bfloat162float(a));
}

// ---------------- embedding gather ----------------
__global__ void embed_kernel(const int* __restrict__ tokens,
                             const float* __restrict__ emb) {
    int s = blockIdx.x, d = threadIdx.x;
    g_x[s * D + d] = emb[(size_t)tokens[s] * D + d];
}

// ---------------- AstroNorm column stats ----------------
__global__ void stats_kernel(const float* __restrict__ buffers,
                             const float* __restrict__ decays, int l) {
    int d = blockIdx.x, tid = threadIdx.x;
    float s = 0.f, s2 = 0.f;
    for (int i = tid; i < S; i += 256) {
        float v = g_x[i * D + d];
        s += v; s2 += v * v;
    }
    __shared__ float sh[256], sh2[256];
    sh[tid] = s; sh2[tid] = s2;
    __syncthreads();
    for (int off = 128; off > 0; off >>= 1) {
        if (tid < off) { sh[tid] += sh[tid + off]; sh2[tid] += sh2[tid + off]; }
        __syncthreads();
    }
    if (tid == 0) {
        float mu = sh[0] / (float)S;
        float var = (sh2[0] - (float)S * mu * mu) / (float)(S - 1);
        g_mu[d] = mu;
        g_istd[d] = rsqrtf(var + 1e-6f);
        float dec = decays[l];
        float nb = dec * buffers[l * D + d] + (1.f - dec) * mu;
        g_absnb[d] = fabsf(nb);
    }
}

// ---------------- apply AstroNorm + gate scores (warp-shuffle reduce) -----------
__global__ void norm_score_kernel(const float* __restrict__ gate_w, int l) {
    int s = blockIdx.x, d = threadIdx.x;
    float v = g_x[s * D + d];
    float mu = g_mu[d];
    float v2 = (fabsf(v - mu) > g_absnb[d] ? mu : v) * g_istd[d];
    g_x[s * D + d] = v2;
    float p = v2 * gate_w[l * D + d];
    #pragma unroll
    for (int off = 16; off > 0; off >>= 1)
        p += __shfl_down_sync(0xFFFFFFFFu, p, off);
    __shared__ float w[8];
    if ((d & 31) == 0) w[d >> 5] = p;
    __syncthreads();
    if (d == 0) {
        float t = 0.f;
        #pragma unroll
        for (int i = 0; i < 8; i++) t += w[i];
        g_scores[s] = t;
    }
}

// ---------------- k-th largest: parallel order statistic ----------------
__global__ void select_kernel() {
    __shared__ float sc[S];
    __shared__ int sgt[32][8], sge[32][8];
    int tid = threadIdx.x;
    for (int i = tid; i < S; i += 256) sc[i] = g_scores[i];
    __syncthreads();
    int c = tid >> 3, part = tid & 7;
    float v = sc[blockIdx.x * 32 + c];
    int gt = 0, ge = 0;
    int j0 = part * 512;
    #pragma unroll 8
    for (int j = j0; j < j0 + 512; j++) {
        float u = sc[j];
        gt += (u > v);
        ge += (u >= v);
    }
    sgt[c][part] = gt; sge[c][part] = ge;
    __syncthreads();
    if (part == 0) {
        int GT = 0, GE = 0;
        #pragma unroll
        for (int p = 0; p < 8; p++) { GT += sgt[c][p]; GE += sge[c][p]; }
        if (GT < KGATE && GE >= KGATE) g_thr[0] = v;
    }
}

// ---------- sparsity gate + routing mask (float4 reduce, no limb writes) --------
__global__ void gate_mask_kernel(const float* __restrict__ gating_W,
                                 const float* __restrict__ gating_b, int l) {
    int s = blockIdx.x, d = threadIdx.x;
    bool keep = g_scores[s] > g_thr[0];
    float v = keep ? g_x[s * D + d] : 0.f;
    g_x[s * D + d] = v;

    __shared__ float4 sh4[256];
    const float* W = gating_W + l * E * D;
    sh4[d] = make_float4(v * W[d], v * W[D + d], v * W[2 * D + d], v * W[3 * D + d]);
    __syncthreads();
    for (int off = 128; off > 0; off >>= 1) {
        if (d < off) {
            float4 x = sh4[d], y = sh4[d + off];
            sh4[d] = make_float4(x.x + y.x, x.y + y.y, x.z + y.z, x.w + y.w);
        }
        __syncthreads();
    }
    if (d == 0) {
        float gs[E] = { sh4[0].x + gating_b[l * E + 0],
                        sh4[0].y + gating_b[l * E + 1],
                        sh4[0].z + gating_b[l * E + 2],
                        sh4[0].w + gating_b[l * E + 3] };
        float best = gs[0]; int excl = 0;
        #pragma unroll
        for (int e = 1; e < E; e++)
            if (gs[e] <= best) { best = gs[e]; excl = e; }
        #pragma unroll
        for (int e = 0; e < E; e++)
            g_mask[s * E + e] = (e == excl) ? 0.f : 1.f;
    }
}

// ---------------- combine expert outputs with mask ----------------
__global__ void combine_kernel(const float* __restrict__ exp_b, int l) {
    int s = blockIdx.x, o = threadIdx.x;
    float acc = 0.f;
    #pragma unroll
    for (int e = 0; e < E; e++) {
        float m = g_mask[s * E + e];
        acc += m * (g_y[(size_t)s * (E * D) + e * D + o] + exp_b[l * E * D + e * D + o]);
    }
    g_x[s * D + o] = acc;
}

// ---------------- final LayerNorm + 2-limb split for head ----------------
__global__ void ln_kernel(const float* __restrict__ g, const float* __restrict__ b) {
    int s = blockIdx.x, d = threadIdx.x;
    float v = g_x[s * D + d];
    __shared__ float sh[256];
    sh[d] = v;
    __syncthreads();
    for (int off = 128; off > 0; off >>= 1) {
        if (d < off) sh[d] += sh[d + off];
        __syncthreads();
    }
    float mean = sh[0] / (float)D;
    __syncthreads();
    float c = v - mean;
    sh[d] = c * c;
    __syncthreads();
    for (int off = 128; off > 0; off >>= 1) {
        if (d < off) sh[d] += sh[d + off];
        __syncthreads();
    }
    float var = sh[0] / (float)D;
    float y = c * rsqrtf(var + 1e-5f) * g[d] + b[d];
    __nv_bfloat16 h = __float2bfloat16(y);
    g_xs0[s * D + d] = h;
    g_xs1[s * D + d] = __float2bfloat16(y - __bfloat162float(h));
}

// ---------------- launch ----------------
extern "C" void kernel_launch(void* const* d_in, const int* in_sizes, int n_in,
                              void* d_out, int out_size) {
    const int*   tokens   = (const int*)  d_in[0];
    const float* emb      = (const float*)d_in[1];
    const float* buffers  = (const float*)d_in[2];
    const float* decays   = (const float*)d_in[3];
    const float* gate_w   = (const float*)d_in[4];
    const float* gating_W = (const float*)d_in[5];
    const float* gating_b = (const float*)d_in[6];
    const float* exp_W    = (const float*)d_in[7];
    const float* exp_b    = (const float*)d_in[8];
    const float* ln_g     = (const float*)d_in[9];
    const float* ln_b     = (const float*)d_in[10];
    const float* head_W   = (const float*)d_in[11];
    const float* head_b   = (const float*)d_in[12];
    float* out = (float*)d_out;

    float *xp, *yp;
    cudaGetSymbolAddress((void**)&xp, g_x);
    cudaGetSymbolAddress((void**)&yp, g_y);
    __nv_bfloat16 *xs0, *xs1, *wh0, *wh1;
    cudaGetSymbolAddress((void**)&xs0, g_xs0);
    cudaGetSymbolAddress((void**)&xs1, g_xs1);
    cudaGetSymbolAddress((void**)&wh0, g_wh0);
    cudaGetSymbolAddress((void**)&wh1, g_wh1);

    const int SMEMH = 2 * HSTAGE;   // 221184
    cudaFuncSetAttribute(head_gemm, cudaFuncAttributeMaxDynamicSharedMemorySize, SMEMH);

    // head W limb split (every call; deterministic)
    split2_kernel<<<(V * D + 255) / 256, 256>>>(head_W, wh0, wh1, V * D);

    embed_kernel<<<S, 256>>>(tokens, emb);

    for (int l = 0; l < L; l++) {
        stats_kernel<<<D, 256>>>(buffers, decays, l);
        norm_score_kernel<<<S, 256>>>(gate_w, l);
        select_kernel<<<128, 256>>>();
        gate_mask_kernel<<<S, 256>>>(gating_W, gating_b, l);
        dim3 ge((E * D) / BN, S / BM);   // (8, 32)
        sgemm_nt<<<ge, 256>>>(xp, exp_W + (size_t)l * E * D * D, yp, S, E * D, D);
        combine_kernel<<<S, 256>>>(exp_b, l);
    }

    ln_kernel<<<S, 256>>>(ln_g, ln_b);

    dim3 gh(V / 256, S / 128);           // (125, 32)
    head_gemm<<<gh, 256, SMEMH>>>(xs0, xs1, wh0, wh1, out, head_b);
}

// round 9
// speedup vs baseline: 3.8674x; 1.8599x over previous
#include <cuda_runtime.h>
#include <cuda_bf16.h>
#include <cstdint>

#define S 4096
#define D 256
#define L 4
#define E 4
#define V 32000
#define KGATE 2201   // int(4096 * sigmoid(0.15))

// ---------------- device scratch (no allocations allowed) ----------------
__device__ float g_x[S * D];            // fp32 activations
__device__ float g_y[S * E * D];        // all-expert outputs
__device__ float g_scores[S];
__device__ float g_mu[D];
__device__ float g_istd[D];
__device__ float g_absnb[D];
__device__ float g_thr[1];
__device__ float g_mask[S * E];
__device__ int   g_idx[S];              // permutation: kept rows first
__device__ int   g_keepf[S];            // keep flag per token
__device__ int   g_nk[1];               // number of kept tokens
__device__ float g_fill[V];             // head output row for dropped tokens
__device__ __nv_bfloat16 g_xs0[S * D], g_xs1[S * D];   // LN'd x limbs (head A)
__device__ __nv_bfloat16 g_wh0[V * D], g_wh1[V * D];   // head W limbs

// ================= PTX helpers (sm_80-class, legal on plain sm_103) ==========
__device__ __forceinline__ uint32_t smem_u32(const void* p) {
    uint32_t a;
    asm("{ .reg .u64 t; cvta.to.shared.u64 t, %1; cvt.u32.u64 %0, t; }" : "=r"(a) : "l"(p));
    return a;
}
__device__ __forceinline__ void cp_async16(uint32_t s, const void* g) {
    asm volatile("cp.async.cg.shared.global [%0], [%1], 16;" :: "r"(s), "l"(g));
}
__device__ __forceinline__ void cp_commit() {
    asm volatile("cp.async.commit_group;");
}
template <int N>
__device__ __forceinline__ void cp_wait() {
    asm volatile("cp.async.wait_group %0;" :: "n"(N));
}
__device__ __forceinline__ uint32_t lds32(uint32_t addr) {
    uint32_t v;
    asm volatile("ld.shared.b32 %0, [%1];" : "=r"(v) : "r"(addr));
    return v;
}
__device__ __forceinline__ void mma16816(float* c, const uint32_t* a, const uint32_t* b) {
    asm volatile("mma.sync.aligned.m16n8k16.row.col.f32.bf16.bf16.f32 "
                 "{%0,%1,%2,%3}, {%4,%5,%6,%7}, {%8,%9}, {%0,%1,%2,%3};"
                 : "+f"(c[0]), "+f"(c[1]), "+f"(c[2]), "+f"(c[3])
                 : "r"(a[0]), "r"(a[1]), "r"(a[2]), "r"(a[3]), "r"(b[0]), "r"(b[1]));
}

// =============== head GEMM (proven math + row gather/scatter) ====================
#define ROWB 144                        // 64 bf16 + pad = 144 B per smem row
#define ATILE (128 * ROWB)              // 18432 B
#define BTILE (256 * ROWB)              // 36864 B
#define HSTAGE (2 * ATILE + 2 * BTILE)  // 110592 B per stage
__global__ __launch_bounds__(256, 1) void head_gemm(
    const __nv_bfloat16* __restrict__ A0, const __nv_bfloat16* __restrict__ A1,
    const __nv_bfloat16* __restrict__ B0, const __nv_bfloat16* __restrict__ B1,
    float* __restrict__ C, const float* __restrict__ bias)
{
    if ((int)(blockIdx.y * 128) >= g_nk[0]) return;   // tile fully beyond kept rows
    extern __shared__ char smem[];
    __shared__ int ridx[128];
    uint32_t sbase = smem_u32(smem);
    int tid = threadIdx.x, lane = tid & 31, wid = tid >> 5;
    int grp = lane >> 2, tig = lane & 3;
    int m_off = (wid >> 2) * 64;
    int n_off = (wid & 3) * 64;
    int col0 = blockIdx.x * 256;
    const int N = V;
    const __nv_bfloat16* Ap[2] = {A0, A1};
    const __nv_bfloat16* Bp[2] = {B0, B1};

    if (tid < 128) ridx[tid] = g_idx[blockIdx.y * 128 + tid];
    __syncthreads();

    float acc[4][8][4];
    #pragma unroll
    for (int i = 0; i < 4; i++)
        #pragma unroll
        for (int j = 0; j < 8; j++)
            #pragma unroll
            for (int k = 0; k < 4; k++) acc[i][j][k] = 0.f;

    auto load_stage = [&](int ch) {
        uint32_t sb = sbase + (ch & 1) * HSTAGE;
        int k0 = ch * 64;
        #pragma unroll
        for (int i = 0; i < 8; i++) {
            int idx = tid + i * 256;
            int r = idx >> 3, c8 = idx & 7;
            int limb = r >> 7, row = r & 127;
            uint32_t so = limb * ATILE + row * ROWB + c8 * 16;
            cp_async16(sb + so, Ap[limb] + (size_t)ridx[row] * 256 + k0 + c8 * 8);
        }
        #pragma unroll
        for (int i = 0; i < 16; i++) {
            int idx = tid + i * 256;
            int r = idx >> 3, c8 = idx & 7;
            int limb = r >> 8, row = r & 255;
            uint32_t so = 2 * ATILE + limb * BTILE + row * ROWB + c8 * 16;
            cp_async16(sb + so, Bp[limb] + (size_t)(col0 + row) * 256 + k0 + c8 * 8);
        }
    };

    load_stage(0); cp_commit();

    #pragma unroll
    for (int ch = 0; ch < 4; ch++) {
        if (ch + 1 < 4) { load_stage(ch + 1); cp_commit(); cp_wait<1>(); }
        else           { cp_wait<0>(); }
        __syncthreads();

        uint32_t sb = sbase + (ch & 1) * HSTAGE;
        #pragma unroll
        for (int ks = 0; ks < 4; ks++) {
            #pragma unroll
            for (int p = 0; p < 3; p++) {
                const int ta = (p == 2) ? 1 : 0;
                const int tb = (p == 1) ? 1 : 0;
                uint32_t a[4][4];
                #pragma unroll
                for (int mt = 0; mt < 4; mt++) {
                    uint32_t base = sb + ta * ATILE
                                  + (m_off + mt * 16 + grp) * ROWB + ks * 32 + tig * 4;
                    a[mt][0] = lds32(base);
                    a[mt][1] = lds32(base + 8 * ROWB);
                    a[mt][2] = lds32(base + 16);
                    a[mt][3] = lds32(base + 8 * ROWB + 16);
                }
                #pragma unroll
                for (int nt = 0; nt < 8; nt++) {
                    uint32_t base = sb + 2 * ATILE + tb * BTILE
                                  + (n_off + nt * 8 + grp) * ROWB + ks * 32 + tig * 4;
                    uint32_t b[2];
                    b[0] = lds32(base);
                    b[1] = lds32(base + 16);
                    #pragma unroll
                    for (int mt = 0; mt < 4; mt++)
                        mma16816(acc[mt][nt], a[mt], b);
                }
            }
        }
        __syncthreads();
    }

    int rl = m_off + grp;
    int cb = col0 + n_off + tig * 2;
    #pragma unroll
    for (int mt = 0; mt < 4; mt++) {
        int r0 = ridx[rl + mt * 16], r1 = ridx[rl + mt * 16 + 8];
        #pragma unroll
        for (int nt = 0; nt < 8; nt++) {
            int cc = cb + nt * 8;
            float b0 = bias[cc], b1 = bias[cc + 1];
            float2 v0 = make_float2(acc[mt][nt][0] + b0, acc[mt][nt][1] + b1);
            float2 v1 = make_float2(acc[mt][nt][2] + b0, acc[mt][nt][3] + b1);
            *(float2*)(C + (size_t)r0 * N + cc) = v0;
            *(float2*)(C + (size_t)r1 * N + cc) = v1;
        }
    }
}

// --------- fp32 SGEMM, gather/scatter rows (proven per-row math) ----------------
#define BM 128
#define BN 128
#define BK 16
#define TM 8
#define TN 8
__global__ __launch_bounds__(256) void sgemm_gs(const float* __restrict__ A,
                                               const float* __restrict__ B,
                                               float* __restrict__ C,
                                               int M, int N, int K) {
    if ((int)(blockIdx.y * BM) >= g_nk[0]) return;
    __shared__ float As[BK][BM];
    __shared__ float Bs[BK][BN];
    __shared__ int ridx[BM];
    int tid = threadIdx.x;
    int tx = tid & 15, ty = tid >> 4;
    int col0 = blockIdx.x * BN;
    if (tid < BM) ridx[tid] = g_idx[blockIdx.y * BM + tid];
    __syncthreads();
    float acc[TM][TN];
    #pragma unroll
    for (int i = 0; i < TM; i++)
        #pragma unroll
        for (int j = 0; j < TN; j++) acc[i][j] = 0.f;

    for (int k0 = 0; k0 < K; k0 += BK) {
        #pragma unroll
        for (int i = 0; i < 2; i++) {
            int idx = tid + i * 256;
            int r = idx >> 2;
            int c4 = (idx & 3) << 2;
            float4 va = *(const float4*)(A + (size_t)ridx[r] * K + k0 + c4);
            As[c4 + 0][r] = va.x; As[c4 + 1][r] = va.y;
            As[c4 + 2][r] = va.z; As[c4 + 3][r] = va.w;
            float4 vb = *(const float4*)(B + (size_t)(col0 + r) * K + k0 + c4);
            Bs[c4 + 0][r] = vb.x; Bs[c4 + 1][r] = vb.y;
            Bs[c4 + 2][r] = vb.z; Bs[c4 + 3][r] = vb.w;
        }
        __syncthreads();
        #pragma unroll
        for (int kk = 0; kk < BK; kk++) {
            float ra[TM], rb[TN];
            #pragma unroll
            for (int i = 0; i < TM; i++) ra[i] = As[kk][ty * TM + i];
            #pragma unroll
            for (int j = 0; j < TN; j++) rb[j] = Bs[kk][tx * TN + j];
            #pragma unroll
            for (int i = 0; i < TM; i++)
                #pragma unroll
                for (int j = 0; j < TN; j++)
                    acc[i][j] += ra[i] * rb[j];
        }
        __syncthreads();
    }
    #pragma unroll
    for (int i = 0; i < TM; i++) {
        int r = ridx[ty * TM + i];
        #pragma unroll
        for (int j = 0; j < TN; j += 4) {
            int c = col0 + tx * TN + j;
            float4 v = make_float4(acc[i][j], acc[i][j + 1], acc[i][j + 2], acc[i][j + 3]);
            *(float4*)(C + (size_t)r * N + c) = v;
        }
    }
}

// ---------------- head W limb split ----------------
__global__ void split2_kernel(const float* __restrict__ src,
                              __nv_bfloat16* __restrict__ h0,
                              __nv_bfloat16* __restrict__ h1, int n) {
    int i = blockIdx.x * 256 + threadIdx.x;
    if (i >= n) return;
    float v = src[i];
    __nv_bfloat16 a = __float2bfloat16(v);
    h0[i] = a;
    h1[i] = __float2bfloat16(v - __bfloat162float(a));
}

// ------- head fill row: out row for x==0 tokens = (LN of zero row)·W^T + head_b --
// LN of an all-zero row: mean 0, var 0 -> y[d] = 0*rsqrt(1e-5)*g[d] + b[d] = ln_b[d]
__global__ void fill_row_kernel(const float* __restrict__ ln_b,
                                const float* __restrict__ head_W,
                                const float* __restrict__ head_b) {
    int c = blockIdx.x * 256 + threadIdx.x;
    if (c >= V) return;
    float acc = 0.f;
    const float* w = head_W + (size_t)c * D;
    #pragma unroll 8
    for (int d = 0; d < D; d++) acc += ln_b[d] * w[d];
    g_fill[c] = acc + head_b[c];
}

// ---------------- fill dropped-token output rows ----------------
__global__ void bias_fill_kernel(float* __restrict__ out) {
    int s = blockIdx.x;
    if (g_keepf[s]) return;
    float* dst = out + (size_t)s * V;
    for (int c = threadIdx.x * 4; c < V; c += 1024) {
        float4 v = *(const float4*)(g_fill + c);
        *(float4*)(dst + c) = v;
    }
}

// ---------------- embedding gather ----------------
__global__ void embed_kernel(const int* __restrict__ tokens,
                             const float* __restrict__ emb) {
    int s = blockIdx.x, d = threadIdx.x;
    g_x[s * D + d] = emb[(size_t)tokens[s] * D + d];
}

// ---------------- AstroNorm column stats ----------------
__global__ void stats_kernel(const float* __restrict__ buffers,
                             const float* __restrict__ decays, int l) {
    int d = blockIdx.x, tid = threadIdx.x;
    float s = 0.f, s2 = 0.f;
    for (int i = tid; i < S; i += 256) {
        float v = g_x[i * D + d];
        s += v; s2 += v * v;
    }
    __shared__ float sh[256], sh2[256];
    sh[tid] = s; sh2[tid] = s2;
    __syncthreads();
    for (int off = 128; off > 0; off >>= 1) {
        if (tid < off) { sh[tid] += sh[tid + off]; sh2[tid] += sh2[tid + off]; }
        __syncthreads();
    }
    if (tid == 0) {
        float mu = sh[0] / (float)S;
        float var = (sh2[0] - (float)S * mu * mu) / (float)(S - 1);
        g_mu[d] = mu;
        g_istd[d] = rsqrtf(var + 1e-6f);
        float dec = decays[l];
        float nb = dec * buffers[l * D + d] + (1.f - dec) * mu;
        g_absnb[d] = fabsf(nb);
    }
}

// ---------------- apply AstroNorm + gate scores (warp-shuffle reduce) -----------
__global__ void norm_score_kernel(const float* __restrict__ gate_w, int l) {
    int s = blockIdx.x, d = threadIdx.x;
    float v = g_x[s * D + d];
    float mu = g_mu[d];
    float v2 = (fabsf(v - mu) > g_absnb[d] ? mu : v) * g_istd[d];
    g_x[s * D + d] = v2;
    float p = v2 * gate_w[l * D + d];
    #pragma unroll
    for (int off = 16; off > 0; off >>= 1)
        p += __shfl_down_sync(0xFFFFFFFFu, p, off);
    __shared__ float w[8];
    if ((d & 31) == 0) w[d >> 5] = p;
    __syncthreads();
    if (d == 0) {
        float t = 0.f;
        #pragma unroll
        for (int i = 0; i < 8; i++) t += w[i];
        g_scores[s] = t;
    }
}

// ---------------- k-th largest: parallel order statistic ----------------
__global__ void select_kernel() {
    __shared__ float sc[S];
    __shared__ int sgt[32][8], sge[32][8];
    int tid = threadIdx.x;
    for (int i = tid; i < S; i += 256) sc[i] = g_scores[i];
    __syncthreads();
    int c = tid >> 3, part = tid & 7;
    float v = sc[blockIdx.x * 32 + c];
    int gt = 0, ge = 0;
    int j0 = part * 512;
    #pragma unroll 8
    for (int j = j0; j < j0 + 512; j++) {
        float u = sc[j];
        gt += (u > v);
        ge += (u >= v);
    }
    sgt[c][part] = gt; sge[c][part] = ge;
    __syncthreads();
    if (part == 0) {
        int GT = 0, GE = 0;
        #pragma unroll
        for (int p = 0; p < 8; p++) { GT += sgt[c][p]; GE += sge[c][p]; }
        if (GT < KGATE && GE >= KGATE) g_thr[0] = v;
    }
}

// --------- stable partition: kept token indices first, then dropped -------------
__global__ void partition_kernel() {   // 1 block x 1024 threads
    __shared__ int sc[1024];
    __shared__ int s_nk;
    int tid = threadIdx.x;
    float thr = g_thr[0];
    int base = tid * 4;
    int f[4], cnt = 0;
    #pragma unroll
    for (int j = 0; j < 4; j++) {
        f[j] = (g_scores[base + j] > thr) ? 1 : 0;
        cnt += f[j];
    }
    sc[tid] = cnt;
    __syncthreads();
    for (int off = 1; off < 1024; off <<= 1) {
        int v = (tid >= off) ? sc[tid - off] : 0;
        __syncthreads();
        sc[tid] += v;
        __syncthreads();
    }
    if (tid == 1023) s_nk = sc[1023];
    __syncthreads();
    int nk = s_nk;
    int kb = sc[tid] - cnt;          // kept before my first element
    #pragma unroll
    for (int j = 0; j < 4; j++) {
        int s = base + j;
        if (f[j]) { g_idx[kb] = s; g_keepf[s] = 1; kb++; }
        else      { g_idx[nk + (s - kb)] = s; g_keepf[s] = 0; }
    }
    if (tid == 0) g_nk[0] = nk;
}

// ---------- routing mask (float4 reduce); no x write needed anymore -------------
__global__ void gate_mask_kernel(const float* __restrict__ gating_W,
                                 const float* __restrict__ gating_b, int l) {
    int s = blockIdx.x, d = threadIdx.x;
    bool keep = g_scores[s] > g_thr[0];
    float v = keep ? g_x[s * D + d] : 0.f;

    __shared__ float4 sh4[256];
    const float* W = gating_W + l * E * D;
    sh4[d] = make_float4(v * W[d], v * W[D + d], v * W[2 * D + d], v * W[3 * D + d]);
    __syncthreads();
    for (int off = 128; off > 0; off >>= 1) {
        if (d < off) {
            float4 x = sh4[d], y = sh4[d + off];
            sh4[d] = make_float4(x.x + y.x, x.y + y.y, x.z + y.z, x.w + y.w);
        }
        __syncthreads();
    }
    if (d == 0) {
        float gs[E] = { sh4[0].x + gating_b[l * E + 0],
                        sh4[0].y + gating_b[l * E + 1],
                        sh4[0].z + gating_b[l * E + 2],
                        sh4[0].w + gating_b[l * E + 3] };
        float best = gs[0]; int excl = 0;
        #pragma unroll
        for (int e = 1; e < E; e++)
            if (gs[e] <= best) { best = gs[e]; excl = e; }
        #pragma unroll
        for (int e = 0; e < E; e++)
            g_mask[s * E + e] = (e == excl) ? 0.f : 1.f;
    }
}

// ---------------- combine expert outputs with mask ----------------
// Dropped tokens: x row = 0 -> ys = 0·W + exp_b, so acc = sum m_e * exp_b.
__global__ void combine_kernel(const float* __restrict__ exp_b, int l) {
    int s = blockIdx.x, o = threadIdx.x;
    float acc = 0.f;
    if (g_keepf[s]) {
        #pragma unroll
        for (int e = 0; e < E; e++) {
            float m = g_mask[s * E + e];
            acc += m * (g_y[(size_t)s * (E * D) + e * D + o] + exp_b[l * E * D + e * D + o]);
        }
    } else {
        #pragma unroll
        for (int e = 0; e < E; e++)
            acc += g_mask[s * E + e] * exp_b[l * E * D + e * D + o];
    }
    g_x[s * D + o] = acc;
}

// ---------------- final LayerNorm + 2-limb split for head ----------------
__global__ void ln_kernel(const float* __restrict__ g, const float* __restrict__ b) {
    int s = blockIdx.x, d = threadIdx.x;
    float v = g_x[s * D + d];
    __shared__ float sh[256];
    sh[d] = v;
    __syncthreads();
    for (int off = 128; off > 0; off >>= 1) {
        if (d < off) sh[d] += sh[d + off];
        __syncthreads();
    }
    float mean = sh[0] / (float)D;
    __syncthreads();
    float c = v - mean;
    sh[d] = c * c;
    __syncthreads();
    for (int off = 128; off > 0; off >>= 1) {
        if (d < off) sh[d] += sh[d + off];
        __syncthreads();
    }
    float var = sh[0] / (float)D;
    float y = c * rsqrtf(var + 1e-5f) * g[d] + b[d];
    __nv_bfloat16 h = __float2bfloat16(y);
    g_xs0[s * D + d] = h;
    g_xs1[s * D + d] = __float2bfloat16(y - __bfloat162float(h));
}

// ---------------- launch ----------------
extern "C" void kernel_launch(void* const* d_in, const int* in_sizes, int n_in,
                              void* d_out, int out_size) {
    const int*   tokens   = (const int*)  d_in[0];
    const float* emb      = (const float*)d_in[1];
    const float* buffers  = (const float*)d_in[2];
    const float* decays   = (const float*)d_in[3];
    const float* gate_w   = (const float*)d_in[4];
    const float* gating_W = (const float*)d_in[5];
    const float* gating_b = (const float*)d_in[6];
    const float* exp_W    = (const float*)d_in[7];
    const float* exp_b    = (const float*)d_in[8];
    const float* ln_g     = (const float*)d_in[9];
    const float* ln_b     = (const float*)d_in[10];
    const float* head_W   = (const float*)d_in[11];
    const float* head_b   = (const float*)d_in[12];
    float* out = (float*)d_out;

    float *xp, *yp;
    cudaGetSymbolAddress((void**)&xp, g_x);
    cudaGetSymbolAddress((void**)&yp, g_y);
    __nv_bfloat16 *xs0, *xs1, *wh0, *wh1;
    cudaGetSymbolAddress((void**)&xs0, g_xs0);
    cudaGetSymbolAddress((void**)&xs1, g_xs1);
    cudaGetSymbolAddress((void**)&wh0, g_wh0);
    cudaGetSymbolAddress((void**)&wh1, g_wh1);

    const int SMEMH = 2 * HSTAGE;   // 221184
    cudaFuncSetAttribute(head_gemm, cudaFuncAttributeMaxDynamicSharedMemorySize, SMEMH);

    // head W limb split + dropped-row fill template (independent; run up front)
    split2_kernel<<<(V * D + 255) / 256, 256>>>(head_W, wh0, wh1, V * D);
    fill_row_kernel<<<(V + 255) / 256, 256>>>(ln_b, head_W, head_b);

    embed_kernel<<<S, 256>>>(tokens, emb);

    for (int l = 0; l < L; l++) {
        stats_kernel<<<D, 256>>>(buffers, decays, l);
        norm_score_kernel<<<S, 256>>>(gate_w, l);
        select_kernel<<<128, 256>>>();
        partition_kernel<<<1, 1024>>>();
        gate_mask_kernel<<<S, 256>>>(gating_W, gating_b, l);
        dim3 ge((E * D) / BN, S / BM);   // (8, 32); tiles past NK early-exit
        sgemm_gs<<<ge, 256>>>(xp, exp_W + (size_t)l * E * D * D, yp, S, E * D, D);
        combine_kernel<<<S, 256>>>(exp_b, l);
    }

    ln_kernel<<<S, 256>>>(ln_g, ln_b);

    dim3 gh(V / 256, S / 128);           // (125, 32); tiles past NK4 early-exit
    head_gemm<<<gh, 256, SMEMH>>>(xs0, xs1, wh0, wh1, out, head_b);
    bias_fill_kernel<<<S, 256>>>(out);
}